// round 12
// baseline (speedup 1.0000x reference)
#include <cuda_runtime.h>
#include <cuda_fp16.h>
#include <cstdint>

#define T_DIM 12
#define B_DIM 16
#define N_DIM 2048
#define D_DIM 128
#define TD    1536   // T_DIM * D_DIM
#define CAND  8      // candidates kept per row for exact refinement

// Scratch (device globals: allocation-free per harness rules)
__device__ __align__(256) __half g_xn[(size_t)B_DIM * N_DIM * TD];  // ~100 MB (fp16 normalized)
__device__ float  g_rn[(size_t)B_DIM * N_DIM];                      // 1/norm per row
__device__ float2 g_part[(size_t)B_DIM * 16 * 128 * 16 * CAND];     // 33.5 MB partials
__device__ int    g_cand[(size_t)B_DIM * N_DIM * CAND];             // 1 MB

// insertion into a descending top-8 register list
#define INS(tv, ti, VAL, J)                                             \
    if ((VAL) > tv[CAND - 1]) {                                         \
        tv[CAND - 1] = (VAL); ti[CAND - 1] = (J);                       \
        _Pragma("unroll")                                               \
        for (int s_ = CAND - 1; s_ > 0; --s_)                           \
            if (tv[s_] > tv[s_ - 1]) {                                  \
                float a_ = tv[s_]; tv[s_] = tv[s_ - 1]; tv[s_ - 1] = a_;\
                int   c_ = ti[s_]; ti[s_] = ti[s_ - 1]; ti[s_ - 1] = c_;\
            }                                                           \
    }

// ---------------------------------------------------------------------------
// Kernel 1: permute [T,B,N,D] -> [B,N,T*D], row-normalize -> fp16; store 1/norm
// ---------------------------------------------------------------------------
__global__ void k_normalize(const float* __restrict__ x) {
    int bn = blockIdx.x;
    int b = bn >> 11, n = bn & (N_DIM - 1);
    int d = threadIdx.x;  // 128 threads = D_DIM
    float vals[T_DIM];
    float ss = 0.f;
#pragma unroll
    for (int t = 0; t < T_DIM; ++t) {
        float v = x[(((size_t)t * B_DIM + b) * N_DIM + n) * D_DIM + d];
        vals[t] = v;
        ss += v * v;
    }
#pragma unroll
    for (int off = 16; off; off >>= 1) ss += __shfl_xor_sync(0xffffffffu, ss, off);
    __shared__ float sred[4];
    int lane = d & 31, wid = d >> 5;
    if (lane == 0) sred[wid] = ss;
    __syncthreads();
    float tot = sred[0] + sred[1] + sred[2] + sred[3];
    float rn = 1.0f / sqrtf(tot);   // IEEE-rounded
    if (d == 0) g_rn[bn] = rn;
    size_t base = (size_t)bn * TD + d;
#pragma unroll
    for (int t = 0; t < T_DIM; ++t)
        g_xn[base + (size_t)t * D_DIM] = __float2half_rn(vals[t] * rn);
}

// ---------------------------------------------------------------------------
// Kernel 2: fp16 batched symmetric GEMM, f16 accumulators (testing 2x legacy
// HMMA rate), per-chunk fp32 master accumulation. 2-stage cp.async, fused
// thread-per-row/column top-8 epilogue. Upper-triangular tiles only.
// ---------------------------------------------------------------------------
#define BM 128
#define BN 128
#define BK 64
#define NKT (TD / BK)                 // 24
#define NTILE (N_DIM / BM)            // 16
#define NUT (NTILE * (NTILE + 1) / 2) // 136
#define SROW 132                      // fp32 staging stride (16B-aligned rows)
#define SMEM_BYTES (128 * SROW * 4)   // 67584

__device__ __forceinline__ void cp16(uint32_t saddr, const void* gaddr) {
    asm volatile("cp.async.cg.shared.global [%0], [%1], 16;\n" :: "r"(saddr), "l"(gaddr));
}

__global__ void __launch_bounds__(256, 2) k_gemm() {
    extern __shared__ __align__(128) __half sm[];
    uint32_t smem = (uint32_t)__cvta_generic_to_shared(sm);
    // byte layout: A s0 [0,16K) A s1 [16K,32K) B s0 [32K,48K) B s1 [48K,64K)
    int b = blockIdx.z;
    // decode upper-triangular tile index -> (mb, nb), nb >= mb
    int t = blockIdx.x, mb = 0;
    while (t >= NTILE - mb) { t -= NTILE - mb; ++mb; }
    int nb = mb + t;
    int mBase = mb * BM, nBase = nb * BN;

    const __half* Ag = g_xn + (size_t)b * N_DIM * TD + (size_t)mBase * TD;
    const __half* Bg = g_xn + (size_t)b * N_DIM * TD + (size_t)nBase * TD;
    int tid = threadIdx.x;
    int lane = tid & 31, wid = tid >> 5;
    int warpM = wid & 1, warpN = wid >> 1;  // 2 x 4 warps -> warp tile 64x32

    float acc[4][4][4];
#pragma unroll
    for (int mi = 0; mi < 4; ++mi)
#pragma unroll
        for (int ni = 0; ni < 4; ++ni)
#pragma unroll
            for (int r = 0; r < 4; ++r) acc[mi][ni][r] = 0.f;

    auto issue = [&](int stage, int kt) {
        int k0 = kt * BK;
#pragma unroll
        for (int i = 0; i < 4; ++i) {
            int idx = tid + i * 256;         // 0..1023
            int row = idx >> 3, c = idx & 7; // 8 x 16B granules per 128B row
            uint32_t soff = (uint32_t)(row * 128 + ((c ^ (row & 7)) << 4));
            cp16(smem + stage * 16384 + soff, Ag + (size_t)row * TD + k0 + c * 8);
            cp16(smem + 32768 + stage * 16384 + soff, Bg + (size_t)row * TD + k0 + c * 8);
        }
    };

    issue(0, 0);
    asm volatile("cp.async.commit_group;\n");

    for (int kt = 0; kt < NKT; ++kt) {
        asm volatile("cp.async.wait_group 0;\n");
        __syncthreads();
        if (kt + 1 < NKT) {
            issue((kt + 1) & 1, kt + 1);
            asm volatile("cp.async.commit_group;\n");
        }
        int s = kt & 1;

        // f16 accumulators for this K=64 chunk (zeroed each chunk)
        uint32_t dh[4][4][2];
#pragma unroll
        for (int mi = 0; mi < 4; ++mi)
#pragma unroll
            for (int ni = 0; ni < 4; ++ni) { dh[mi][ni][0] = 0u; dh[mi][ni][1] = 0u; }

#pragma unroll
        for (int kk = 0; kk < 4; ++kk) {  // 4 k-steps of 16
            uint32_t af[4][4], bf[4][2];
#pragma unroll
            for (int mi = 0; mi < 4; ++mi) {
                int r = warpM * 64 + mi * 16 + (lane & 15);
                int g = kk * 2 + (lane >> 4);
                uint32_t addr = smem + s * 16384 + r * 128 + ((g ^ (r & 7)) << 4);
                asm volatile("ldmatrix.sync.aligned.m8n8.x4.shared.b16 {%0,%1,%2,%3}, [%4];\n"
                    : "=r"(af[mi][0]), "=r"(af[mi][1]), "=r"(af[mi][2]), "=r"(af[mi][3])
                    : "r"(addr));
            }
#pragma unroll
            for (int ni = 0; ni < 4; ++ni) {
                int r = warpN * 32 + ni * 8 + (lane & 7);
                int g = kk * 2 + ((lane >> 3) & 1);
                uint32_t addr = smem + 32768 + s * 16384 + r * 128 + ((g ^ (r & 7)) << 4);
                asm volatile("ldmatrix.sync.aligned.m8n8.x2.shared.b16 {%0,%1}, [%2];\n"
                    : "=r"(bf[ni][0]), "=r"(bf[ni][1]) : "r"(addr));
            }
#pragma unroll
            for (int mi = 0; mi < 4; ++mi)
#pragma unroll
                for (int ni = 0; ni < 4; ++ni) {
                    asm volatile(
                        "mma.sync.aligned.m16n8k16.row.col.f16.f16.f16.f16 "
                        "{%0,%1}, {%2,%3,%4,%5}, {%6,%7}, {%0,%1};\n"
                        : "+r"(dh[mi][ni][0]), "+r"(dh[mi][ni][1])
                        : "r"(af[mi][0]), "r"(af[mi][1]), "r"(af[mi][2]), "r"(af[mi][3]),
                          "r"(bf[ni][0]), "r"(bf[ni][1]));
                }
        }

        // fold f16 chunk accumulators into fp32 masters
#pragma unroll
        for (int mi = 0; mi < 4; ++mi)
#pragma unroll
            for (int ni = 0; ni < 4; ++ni) {
                float2 lo = __half22float2(*reinterpret_cast<__half2*>(&dh[mi][ni][0]));
                float2 hi = __half22float2(*reinterpret_cast<__half2*>(&dh[mi][ni][1]));
                acc[mi][ni][0] += lo.x;
                acc[mi][ni][1] += lo.y;
                acc[mi][ni][2] += hi.x;
                acc[mi][ni][3] += hi.y;
            }
    }

    // ---- fused epilogue: stage tile, then thread-per-row/column top-8 ----
    float* smf = (float*)sm;
    __syncthreads();   // mainloop buffers dead
#pragma unroll
    for (int mi = 0; mi < 4; ++mi)
#pragma unroll
        for (int ni = 0; ni < 4; ++ni) {
            int r0 = warpM * 64 + mi * 16 + (lane >> 2);
            int c0 = warpN * 32 + ni * 8 + 2 * (lane & 3);
            smf[r0 * SROW + c0]           = acc[mi][ni][0];
            smf[r0 * SROW + c0 + 1]       = acc[mi][ni][1];
            smf[(r0 + 8) * SROW + c0]     = acc[mi][ni][2];
            smf[(r0 + 8) * SROW + c0 + 1] = acc[mi][ni][3];
        }
    __syncthreads();

    float tv[CAND]; int ti[CAND];
#pragma unroll
    for (int q = 0; q < CAND; ++q) { tv[q] = -3.4e38f; ti[q] = -1; }

    if (tid < 128) {
        // row task: row `tid` of block mb, columns nBase + c
        const float4* rowp = (const float4*)(smf + tid * SROW);
#pragma unroll 8
        for (int c4 = 0; c4 < 32; ++c4) {
            float4 v = rowp[c4];
            int jb = nBase + 4 * c4;
            INS(tv, ti, v.x, jb)
            INS(tv, ti, v.y, jb + 1)
            INS(tv, ti, v.z, jb + 2)
            INS(tv, ti, v.w, jb + 3)
        }
        float2* dst = g_part + ((((size_t)b * NTILE + mb) * BM + tid) * NTILE + nb) * CAND;
#pragma unroll
        for (int q = 0; q < CAND; ++q) dst[q] = make_float2(tv[q], __int_as_float(ti[q]));
    } else if (mb != nb) {
        // column task: column `cc` serves row (nBase + cc) of block nb
        int cc = tid - 128;
        const float* colp = smf + cc;
#pragma unroll 8
        for (int r = 0; r < 128; ++r) {
            float v = colp[r * SROW];
            INS(tv, ti, v, mBase + r)
        }
        float2* dst = g_part + ((((size_t)b * NTILE + nb) * BM + cc) * NTILE + mb) * CAND;
#pragma unroll
        for (int q = 0; q < CAND; ++q) dst[q] = make_float2(tv[q], __int_as_float(ti[q]));
    }
}

// ---------------------------------------------------------------------------
// Kernel 3: zero-fill output (overlapped) + merge 16x8 partials -> top-8 ids.
// ---------------------------------------------------------------------------
__global__ void __launch_bounds__(256) k_topk2(float4* __restrict__ out) {
    const unsigned FULL = 0xffffffffu;
    // zero-fill slice: fire-and-forget stores, overlap with merge below
    {
        size_t base = (size_t)blockIdx.x * 4096 + threadIdx.x;  // 4096 float4 per block
        float4 z = make_float4(0.f, 0.f, 0.f, 0.f);
#pragma unroll
        for (int i = 0; i < 16; ++i) out[base + (size_t)i * 256] = z;
    }

    int w = threadIdx.x >> 5, lane = threadIdx.x & 31;
    int gw = blockIdx.x * 8 + w;                 // global row id over B*N
    const float2* part = g_part + (size_t)gw * (NTILE * CAND);  // 128 contiguous pairs

    float tv[CAND]; int ti[CAND];
#pragma unroll
    for (int q = 0; q < CAND; ++q) { tv[q] = -3.4e38f; ti[q] = -1; }
#pragma unroll
    for (int i = 0; i < 4; ++i) {
        float2 p = part[lane + i * 32];
        INS(tv, ti, p.x, __float_as_int(p.y))
    }
    int out_idx[CAND];
#pragma unroll
    for (int s = 0; s < CAND; ++s) {
        float best = tv[0];
        int bl = lane;
#pragma unroll
        for (int o = 16; o; o >>= 1) {
            float ov = __shfl_xor_sync(FULL, best, o);
            int obl = __shfl_xor_sync(FULL, bl, o);
            if (ov > best || (ov == best && obl < bl)) { best = ov; bl = obl; }
        }
        int bi = __shfl_sync(FULL, ti[0], bl);
        out_idx[s] = bi;
        if (lane == bl) {
#pragma unroll
            for (int q = 0; q < CAND - 1; ++q) { tv[q] = tv[q + 1]; ti[q] = ti[q + 1]; }
            tv[CAND - 1] = -3.4e38f;
        }
    }
    if (lane < CAND) g_cand[(size_t)gw * CAND + lane] = out_idx[lane];
}

// ---------------------------------------------------------------------------
// Kernel 4: exact fp32 re-ranking of the 8 candidates + symmetric scatter.
// Candidate row prefetched into registers BEFORE the srow fill so both load
// phases overlap (R11 was serialized across the barrier).
// ---------------------------------------------------------------------------
__global__ void __launch_bounds__(256) k_refine(const float* __restrict__ x,
                                                float* __restrict__ out) {
    int rowid = blockIdx.x;
    int b = rowid >> 11, r = rowid & (N_DIM - 1);
    __shared__ __align__(16) float srow[TD];
    __shared__ float sdot[CAND];
    __shared__ int   sjj[CAND];

    int w = threadIdx.x >> 5, lane = threadIdx.x & 31;
    int j = g_cand[(size_t)rowid * CAND + w];

    // prefetch candidate row into registers (12 float4 per lane, all in flight)
    float4 xv[12];
#pragma unroll
    for (int i = 0; i < 12; ++i) {
        int e4 = lane + i * 32;
        int t = e4 >> 5, d4 = e4 & 31;
        xv[i] = ((const float4*)(x + (((size_t)t * B_DIM + b) * N_DIM + j) * D_DIM))[d4];
    }

    // srow fill (overlaps with the gathers above)
    for (int i4 = threadIdx.x; i4 < TD / 4; i4 += 256) {
        int t = i4 >> 5, d4 = i4 & 31;
        const float4* src = (const float4*)(x + (((size_t)t * B_DIM + b) * N_DIM + r) * D_DIM);
        *(float4*)(srow + i4 * 4) = src[d4];
    }
    __syncthreads();

    float s = 0.f;
#pragma unroll
    for (int i = 0; i < 12; ++i) {
        float4 rv = *(const float4*)(srow + (lane + i * 32) * 4);
        s = fmaf(rv.x, xv[i].x, s);
        s = fmaf(rv.y, xv[i].y, s);
        s = fmaf(rv.z, xv[i].z, s);
        s = fmaf(rv.w, xv[i].w, s);
    }
#pragma unroll
    for (int o = 16; o; o >>= 1) s += __shfl_xor_sync(0xffffffffu, s, o);
    if (lane == 0) {
        sdot[w] = s * g_rn[rowid] * g_rn[(b << 11) + j];
        sjj[w] = j;
    }
    __syncthreads();

    if (threadIdx.x == 0) {
        float tv[5]; int ti[5];
#pragma unroll
        for (int q = 0; q < 5; ++q) { tv[q] = -3.4e38f; ti[q] = 0; }
        for (int c = 0; c < CAND; ++c) {
            float val = sdot[c]; int jj = sjj[c];
            if (val > tv[4]) {
                tv[4] = val; ti[4] = jj;
#pragma unroll
                for (int q = 4; q > 0; --q) {
                    if (tv[q] > tv[q - 1]) {
                        float a = tv[q]; tv[q] = tv[q - 1]; tv[q - 1] = a;
                        int   d2 = ti[q]; ti[q] = ti[q - 1]; ti[q - 1] = d2;
                    }
                }
            }
        }
#pragma unroll
        for (int q = 0; q < 5; ++q) {
            float val = tv[q];
            int jj = ti[q];
            float lv = (val >= 0.f) ? val : 0.01f * val;  // leaky_relu
            float wgt = lv * 0.5f;                        // symmetric halves
            atomicAdd(out + ((size_t)b * N_DIM + r) * N_DIM + jj, wgt);
            atomicAdd(out + ((size_t)b * N_DIM + jj) * N_DIM + r, wgt);
        }
    }
}

// ---------------------------------------------------------------------------
extern "C" void kernel_launch(void* const* d_in, const int* in_sizes, int n_in,
                              void* d_out, int out_size) {
    const float* x = (const float*)d_in[0];
    float* out = (float*)d_out;

    k_normalize<<<B_DIM * N_DIM, 128>>>(x);

    cudaFuncSetAttribute(k_gemm, cudaFuncAttributeMaxDynamicSharedMemorySize, SMEM_BYTES);
    k_gemm<<<dim3(NUT, 1, B_DIM), 256, SMEM_BYTES>>>();

    k_topk2<<<(B_DIM * N_DIM) / 8, 256>>>((float4*)out);

    k_refine<<<B_DIM * N_DIM, 256>>>(x, out);
}

// round 14
// speedup vs baseline: 1.1539x; 1.1539x over previous
#include <cuda_runtime.h>
#include <cuda_bf16.h>
#include <cstdint>

#define T_DIM 12
#define B_DIM 16
#define N_DIM 2048
#define D_DIM 128
#define TD    1536   // T_DIM * D_DIM
#define CAND  8      // candidates kept per row for exact refinement

// Scratch (device globals: allocation-free per harness rules)
__device__ __align__(256) __nv_bfloat16 g_xn[(size_t)B_DIM * N_DIM * TD]; // ~100 MB
__device__ float  g_rn[(size_t)B_DIM * N_DIM];                            // 1/norm per row
__device__ float2 g_part[(size_t)B_DIM * 16 * 128 * 16 * CAND];           // 33.5 MB partials

// insertion into a descending top-8 register list
#define INS(tv, ti, VAL, J)                                             \
    if ((VAL) > tv[CAND - 1]) {                                         \
        tv[CAND - 1] = (VAL); ti[CAND - 1] = (J);                       \
        _Pragma("unroll")                                               \
        for (int s_ = CAND - 1; s_ > 0; --s_)                           \
            if (tv[s_] > tv[s_ - 1]) {                                  \
                float a_ = tv[s_]; tv[s_] = tv[s_ - 1]; tv[s_ - 1] = a_;\
                int   c_ = ti[s_]; ti[s_] = ti[s_ - 1]; ti[s_ - 1] = c_;\
            }                                                           \
    }

// ---------------------------------------------------------------------------
// Kernel 1: permute [T,B,N,D] -> [B,N,T*D], row-normalize -> bf16; store 1/norm
// ---------------------------------------------------------------------------
__global__ void k_normalize(const float* __restrict__ x) {
    int bn = blockIdx.x;
    int b = bn >> 11, n = bn & (N_DIM - 1);
    int d = threadIdx.x;  // 128 threads = D_DIM
    float vals[T_DIM];
    float ss = 0.f;
#pragma unroll
    for (int t = 0; t < T_DIM; ++t) {
        float v = x[(((size_t)t * B_DIM + b) * N_DIM + n) * D_DIM + d];
        vals[t] = v;
        ss += v * v;
    }
#pragma unroll
    for (int off = 16; off; off >>= 1) ss += __shfl_xor_sync(0xffffffffu, ss, off);
    __shared__ float sred[4];
    int lane = d & 31, wid = d >> 5;
    if (lane == 0) sred[wid] = ss;
    __syncthreads();
    float tot = sred[0] + sred[1] + sred[2] + sred[3];
    float rn = 1.0f / sqrtf(tot);   // IEEE-rounded
    if (d == 0) g_rn[bn] = rn;
    size_t base = (size_t)bn * TD + d;
#pragma unroll
    for (int t = 0; t < T_DIM; ++t)
        g_xn[base + (size_t)t * D_DIM] = __float2bfloat16(vals[t] * rn);
}

// ---------------------------------------------------------------------------
// Kernel 2: bf16 batched symmetric GEMM (2-stage cp.async, 3 CTAs/SM) with
//  - fused zero-fill of the output (prologue; rides the idle DRAM-write path)
//  - fused thread-per-row/column top-8 epilogue
// Upper-triangular CTA tiles only.
// ---------------------------------------------------------------------------
#define BM 128
#define BN 128
#define BK 64
#define NKT (TD / BK)                 // 24
#define NTILE (N_DIM / BM)            // 16
#define NUT (NTILE * (NTILE + 1) / 2) // 136
#define SROW 132                      // fp32 staging stride (16B-aligned rows)
#define SMEM_BYTES (128 * SROW * 4)   // 67584 -> 3 CTAs/SM
#define OUT_N4 ((size_t)B_DIM * N_DIM * N_DIM / 4)   // 67108864 float4
#define GRID_THREADS ((size_t)NUT * B_DIM * 256)     // 557056

__device__ __forceinline__ void cp16(uint32_t saddr, const void* gaddr) {
    asm volatile("cp.async.cg.shared.global [%0], [%1], 16;\n" :: "r"(saddr), "l"(gaddr));
}

__global__ void __launch_bounds__(256) k_gemm(float4* __restrict__ outv) {
    extern __shared__ __align__(128) __nv_bfloat16 sm[];
    uint32_t smem = (uint32_t)__cvta_generic_to_shared(sm);
    // byte layout: A s0 [0,16K) A s1 [16K,32K) B s0 [32K,48K) B s1 [48K,64K)
    int b = blockIdx.z;
    // decode upper-triangular tile index -> (mb, nb), nb >= mb
    int t = blockIdx.x, mb = 0;
    while (t >= NTILE - mb) { t -= NTILE - mb; ++mb; }
    int nb = mb + t;
    int mBase = mb * BM, nBase = nb * BN;

    const __nv_bfloat16* Ag = g_xn + (size_t)b * N_DIM * TD + (size_t)mBase * TD;
    const __nv_bfloat16* Bg = g_xn + (size_t)b * N_DIM * TD + (size_t)nBase * TD;
    int tid = threadIdx.x;
    int lane = tid & 31, wid = tid >> 5;
    int warpM = wid & 1, warpN = wid >> 1;  // 2 x 4 warps -> warp tile 64x32

    float acc[4][4][4];
#pragma unroll
    for (int mi = 0; mi < 4; ++mi)
#pragma unroll
        for (int ni = 0; ni < 4; ++ni)
#pragma unroll
            for (int r = 0; r < 4; ++r) acc[mi][ni][r] = 0.f;

    auto issue = [&](int stage, int kt) {
        int k0 = kt * BK;
#pragma unroll
        for (int i = 0; i < 4; ++i) {
            int idx = tid + i * 256;         // 0..1023
            int row = idx >> 3, c = idx & 7; // 8 x 16B granules per 128B row
            uint32_t soff = (uint32_t)(row * 128 + ((c ^ (row & 7)) << 4));
            cp16(smem + stage * 16384 + soff, Ag + (size_t)row * TD + k0 + c * 8);
            cp16(smem + 32768 + stage * 16384 + soff, Bg + (size_t)row * TD + k0 + c * 8);
        }
    };

    issue(0, 0);
    asm volatile("cp.async.commit_group;\n");

    // ---- fused zero-fill of the output (fire-and-forget, DRAM-path only) ----
    {
        size_t gid = ((size_t)blockIdx.z * NUT + blockIdx.x) * 256 + tid;
        float4 z = make_float4(0.f, 0.f, 0.f, 0.f);
        for (size_t i = gid; i < OUT_N4; i += GRID_THREADS) outv[i] = z;
    }

    for (int kt = 0; kt < NKT; ++kt) {
        asm volatile("cp.async.wait_group 0;\n");
        __syncthreads();
        if (kt + 1 < NKT) {
            issue((kt + 1) & 1, kt + 1);
            asm volatile("cp.async.commit_group;\n");
        }
        int s = kt & 1;
#pragma unroll
        for (int kk = 0; kk < 4; ++kk) {  // 4 k-steps of 16
            uint32_t af[4][4], bf[4][2];
#pragma unroll
            for (int mi = 0; mi < 4; ++mi) {
                int r = warpM * 64 + mi * 16 + (lane & 15);
                int g = kk * 2 + (lane >> 4);
                uint32_t addr = smem + s * 16384 + r * 128 + ((g ^ (r & 7)) << 4);
                asm volatile("ldmatrix.sync.aligned.m8n8.x4.shared.b16 {%0,%1,%2,%3}, [%4];\n"
                    : "=r"(af[mi][0]), "=r"(af[mi][1]), "=r"(af[mi][2]), "=r"(af[mi][3])
                    : "r"(addr));
            }
#pragma unroll
            for (int ni = 0; ni < 4; ++ni) {
                int r = warpN * 32 + ni * 8 + (lane & 7);
                int g = kk * 2 + ((lane >> 3) & 1);
                uint32_t addr = smem + 32768 + s * 16384 + r * 128 + ((g ^ (r & 7)) << 4);
                asm volatile("ldmatrix.sync.aligned.m8n8.x2.shared.b16 {%0,%1}, [%2];\n"
                    : "=r"(bf[ni][0]), "=r"(bf[ni][1]) : "r"(addr));
            }
#pragma unroll
            for (int mi = 0; mi < 4; ++mi)
#pragma unroll
                for (int ni = 0; ni < 4; ++ni) {
                    asm volatile(
                        "mma.sync.aligned.m16n8k16.row.col.f32.bf16.bf16.f32 "
                        "{%0,%1,%2,%3}, {%4,%5,%6,%7}, {%8,%9}, {%0,%1,%2,%3};\n"
                        : "+f"(acc[mi][ni][0]), "+f"(acc[mi][ni][1]),
                          "+f"(acc[mi][ni][2]), "+f"(acc[mi][ni][3])
                        : "r"(af[mi][0]), "r"(af[mi][1]), "r"(af[mi][2]), "r"(af[mi][3]),
                          "r"(bf[ni][0]), "r"(bf[ni][1]));
                }
        }
    }

    // ---- fused epilogue: stage tile, then thread-per-row/column top-8 ----
    float* smf = (float*)sm;
    __syncthreads();   // mainloop buffers dead
#pragma unroll
    for (int mi = 0; mi < 4; ++mi)
#pragma unroll
        for (int ni = 0; ni < 4; ++ni) {
            int r0 = warpM * 64 + mi * 16 + (lane >> 2);
            int c0 = warpN * 32 + ni * 8 + 2 * (lane & 3);
            smf[r0 * SROW + c0]           = acc[mi][ni][0];
            smf[r0 * SROW + c0 + 1]       = acc[mi][ni][1];
            smf[(r0 + 8) * SROW + c0]     = acc[mi][ni][2];
            smf[(r0 + 8) * SROW + c0 + 1] = acc[mi][ni][3];
        }
    __syncthreads();

    float tv[CAND]; int ti[CAND];
#pragma unroll
    for (int q = 0; q < CAND; ++q) { tv[q] = -3.4e38f; ti[q] = -1; }

    if (tid < 128) {
        // row task: row `tid` of block mb, columns nBase + c
        const float4* rowp = (const float4*)(smf + tid * SROW);
#pragma unroll 8
        for (int c4 = 0; c4 < 32; ++c4) {
            float4 v = rowp[c4];
            int jb = nBase + 4 * c4;
            INS(tv, ti, v.x, jb)
            INS(tv, ti, v.y, jb + 1)
            INS(tv, ti, v.z, jb + 2)
            INS(tv, ti, v.w, jb + 3)
        }
        float2* dst = g_part + ((((size_t)b * NTILE + mb) * BM + tid) * NTILE + nb) * CAND;
#pragma unroll
        for (int q = 0; q < CAND; ++q) dst[q] = make_float2(tv[q], __int_as_float(ti[q]));
    } else if (mb != nb) {
        // column task: column `cc` serves row (nBase + cc) of block nb
        int cc = tid - 128;
        const float* colp = smf + cc;
#pragma unroll 8
        for (int r = 0; r < 128; ++r) {
            float v = colp[r * SROW];
            INS(tv, ti, v, mBase + r)
        }
        float2* dst = g_part + ((((size_t)b * NTILE + nb) * BM + cc) * NTILE + mb) * CAND;
#pragma unroll
        for (int q = 0; q < CAND; ++q) dst[q] = make_float2(tv[q], __int_as_float(ti[q]));
    }
}

// ---------------------------------------------------------------------------
// Kernel 3: fused merge + exact refine + symmetric scatter (one block per row).
// Warp 0 merges this row's 128 (val,idx) partials -> top-8 candidates while
// warps 1..7 fill srow from x. Then each warp computes one exact fp32 dot
// (bit-identical for (r,j) and (j,r)), thread 0 ranks top-5 and scatters.
// ---------------------------------------------------------------------------
__global__ void __launch_bounds__(256) k_refine(const float* __restrict__ x,
                                                float* __restrict__ out) {
    const unsigned FULL = 0xffffffffu;
    int rowid = blockIdx.x;
    int b = rowid >> 11, r = rowid & (N_DIM - 1);
    __shared__ __align__(16) float srow[TD];
    __shared__ int   scand[CAND];
    __shared__ float sdot[CAND];
    __shared__ int   sjj[CAND];

    int tid = threadIdx.x;
    int w = tid >> 5, lane = tid & 31;

    if (w == 0) {
        // merge 16 tiles x 8 partials (128 contiguous float2) -> top-8 indices
        const float2* part = g_part + (size_t)rowid * (NTILE * CAND);
        float tv[4]; int ti[4];
#pragma unroll
        for (int q = 0; q < 4; ++q) { tv[q] = -3.4e38f; ti[q] = -1; }
#pragma unroll
        for (int i = 0; i < 4; ++i) {
            float2 p = part[lane + i * 32];
            if (p.x > tv[3]) {
                tv[3] = p.x; ti[3] = __float_as_int(p.y);
#pragma unroll
                for (int s_ = 3; s_ > 0; --s_)
                    if (tv[s_] > tv[s_ - 1]) {
                        float a_ = tv[s_]; tv[s_] = tv[s_ - 1]; tv[s_ - 1] = a_;
                        int c_ = ti[s_]; ti[s_] = ti[s_ - 1]; ti[s_ - 1] = c_;
                    }
            }
        }
#pragma unroll
        for (int s = 0; s < CAND; ++s) {
            float best = tv[0];
            int bl = lane;
#pragma unroll
            for (int o = 16; o; o >>= 1) {
                float ov = __shfl_xor_sync(FULL, best, o);
                int obl = __shfl_xor_sync(FULL, bl, o);
                if (ov > best || (ov == best && obl < bl)) { best = ov; bl = obl; }
            }
            int bi = __shfl_sync(FULL, ti[0], bl);
            if (lane == 0) scand[s] = bi;
            if (lane == bl) {
#pragma unroll
                for (int q = 0; q < 3; ++q) { tv[q] = tv[q + 1]; ti[q] = ti[q + 1]; }
                tv[3] = -3.4e38f;
            }
        }
    } else {
        // warps 1..7 (224 threads) fill srow: 384 float4s
        for (int i4 = tid - 32; i4 < TD / 4; i4 += 224) {
            int t = i4 >> 5, d4 = i4 & 31;
            const float4* src = (const float4*)(x + (((size_t)t * B_DIM + b) * N_DIM + r) * D_DIM);
            *(float4*)(srow + i4 * 4) = src[d4];
        }
    }
    __syncthreads();

    int j = scand[w];
    float s = 0.f;
#pragma unroll
    for (int i = 0; i < 12; ++i) {           // 384 float4 / 32 lanes
        int e4 = lane + i * 32;
        int t = e4 >> 5, d4 = e4 & 31;
        const float4* src = (const float4*)(x + (((size_t)t * B_DIM + b) * N_DIM + j) * D_DIM);
        float4 xv = src[d4];
        float4 rv = *(const float4*)(srow + e4 * 4);
        s = fmaf(rv.x, xv.x, s);
        s = fmaf(rv.y, xv.y, s);
        s = fmaf(rv.z, xv.z, s);
        s = fmaf(rv.w, xv.w, s);
    }
#pragma unroll
    for (int o = 16; o; o >>= 1) s += __shfl_xor_sync(FULL, s, o);
    if (lane == 0) {
        sdot[w] = s * g_rn[rowid] * g_rn[(b << 11) + j];
        sjj[w] = j;
    }
    __syncthreads();

    if (tid == 0) {
        float tv[5]; int ti[5];
#pragma unroll
        for (int q = 0; q < 5; ++q) { tv[q] = -3.4e38f; ti[q] = 0; }
        for (int c = 0; c < CAND; ++c) {
            float val = sdot[c]; int jj = sjj[c];
            if (val > tv[4]) {
                tv[4] = val; ti[4] = jj;
#pragma unroll
                for (int q = 4; q > 0; --q) {
                    if (tv[q] > tv[q - 1]) {
                        float a = tv[q]; tv[q] = tv[q - 1]; tv[q - 1] = a;
                        int   d2 = ti[q]; ti[q] = ti[q - 1]; ti[q - 1] = d2;
                    }
                }
            }
        }
#pragma unroll
        for (int q = 0; q < 5; ++q) {
            float val = tv[q];
            int jj = ti[q];
            float lv = (val >= 0.f) ? val : 0.01f * val;  // leaky_relu
            float wgt = lv * 0.5f;                        // symmetric halves
            atomicAdd(out + ((size_t)b * N_DIM + r) * N_DIM + jj, wgt);
            atomicAdd(out + ((size_t)b * N_DIM + jj) * N_DIM + r, wgt);
        }
    }
}

// ---------------------------------------------------------------------------
extern "C" void kernel_launch(void* const* d_in, const int* in_sizes, int n_in,
                              void* d_out, int out_size) {
    const float* x = (const float*)d_in[0];
    float* out = (float*)d_out;

    k_normalize<<<B_DIM * N_DIM, 128>>>(x);

    cudaFuncSetAttribute(k_gemm, cudaFuncAttributeMaxDynamicSharedMemorySize, SMEM_BYTES);
    k_gemm<<<dim3(NUT, 1, B_DIM), 256, SMEM_BYTES>>>((float4*)out);

    k_refine<<<B_DIM * N_DIM, 256>>>(x, out);
}